// round 2
// baseline (speedup 1.0000x reference)
#include <cuda_runtime.h>
#include <math.h>

// Problem constants
#define BSZ   4096
#define OBS   512
#define ACT_D 64
#define NT    10
#define NE    16
#define DREP  1024
#define DH    1024
#define DKE   512
#define XD    (OBS + ACT_D)   // 576
#define SW    (OBS + NT)      // 522 state width

// ---------------- scratch (static device globals; no allocation) ----------------
__device__ float g_x[BSZ * XD];
__device__ float g_query[BSZ * DKE];
__device__ float g_reph[BSZ * DREP];
__device__ float g_rep[BSZ * DREP];
__device__ float g_hk[(long)NE * BSZ * DH];
__device__ float g_hv[(long)NE * BSZ * DH];
__device__ float g_keys[(long)NE * BSZ * DKE];
__device__ float g_vals[(long)NE * BSZ * DKE];
__device__ float g_tin[BSZ * DKE];
__device__ float g_h1[BSZ * 512];
__device__ float g_h2[BSZ * 256];
__device__ float g_lossrow[BSZ];

// ---------------- prep: x = [state[:, :512], act]; query = tanh(emb[task]) -----
__global__ void prep_kernel(const float* __restrict__ state,
                            const float* __restrict__ act,
                            const float* __restrict__ emb,
                            float* __restrict__ x,
                            float* __restrict__ query) {
    int b = blockIdx.x;
    int tid = threadIdx.x;
    __shared__ int task_s;
    // concat
    for (int i = tid; i < XD; i += blockDim.x) {
        float v = (i < OBS) ? state[(long)b * SW + i] : act[(long)b * ACT_D + (i - OBS)];
        x[(long)b * XD + i] = v;
    }
    if (tid == 0) {
        float best = -1e30f; int idx = 0;
        for (int t = 0; t < NT; t++) {
            float v = state[(long)b * SW + OBS + t];
            if (v > best) { best = v; idx = t; }
        }
        task_s = idx;
    }
    __syncthreads();
    int task = task_s;
    for (int k = tid; k < DKE; k += blockDim.x)
        query[(long)b * DKE + k] = tanhf(emb[task * DKE + k]);
}

// ---------------- classic 128x128x8 SGEMM, row-major, C = A@B + bias ----------
// Batched via blockIdx.z with per-operand strides. Requires:
//   M % 128 == 0, N % 128 == 0 or N % 128 handled by grid, K % 8 == 0, N % 4 == 0.
constexpr int BM = 128, BN = 128, BK = 8, TM = 8, TN = 8;

template <bool RELU>
__global__ __launch_bounds__(256, 2)
void sgemm_kernel(const float* __restrict__ A, const float* __restrict__ B,
                  const float* __restrict__ bias, float* __restrict__ C,
                  int M, int N, int K,
                  long sA, long sB, long sBias, long sC) {
    int z = blockIdx.z;
    A += (long)z * sA;
    B += (long)z * sB;
    bias += (long)z * sBias;
    C += (long)z * sC;

    __shared__ float As[BK][BM];
    __shared__ float Bs[BK][BN];

    int tid = threadIdx.x;
    int m0 = blockIdx.y * BM;
    int n0 = blockIdx.x * BN;

    int arow = tid >> 1;            // 0..127
    int aseg = (tid & 1) * 4;       // 0 or 4
    int brow = tid >> 5;            // 0..7
    int bcol = (tid & 31) * 4;      // 0..124

    int ty = tid >> 4, tx = tid & 15;

    const float* Aptr = A + (long)(m0 + arow) * K + aseg;
    const float* Bptr = B + (long)brow * N + n0 + bcol;

    float acc[TM][TN];
#pragma unroll
    for (int i = 0; i < TM; i++)
#pragma unroll
        for (int j = 0; j < TN; j++) acc[i][j] = 0.0f;

    for (int k0 = 0; k0 < K; k0 += BK) {
        float4 av = *reinterpret_cast<const float4*>(Aptr + k0);
        float4 bv = *reinterpret_cast<const float4*>(Bptr + (long)k0 * N);
        As[aseg + 0][arow] = av.x;
        As[aseg + 1][arow] = av.y;
        As[aseg + 2][arow] = av.z;
        As[aseg + 3][arow] = av.w;
        *reinterpret_cast<float4*>(&Bs[brow][bcol]) = bv;
        __syncthreads();

#pragma unroll
        for (int k = 0; k < BK; k++) {
            float ra[TM], rb[TN];
#pragma unroll
            for (int i = 0; i < TM; i++) ra[i] = As[k][ty * TM + i];
#pragma unroll
            for (int j = 0; j < TN; j++) rb[j] = Bs[k][tx * TN + j];
#pragma unroll
            for (int i = 0; i < TM; i++)
#pragma unroll
                for (int j = 0; j < TN; j++) acc[i][j] += ra[i] * rb[j];
        }
        __syncthreads();
    }

#pragma unroll
    for (int i = 0; i < TM; i++) {
        long row = (long)(m0 + ty * TM + i) * N;
#pragma unroll
        for (int j = 0; j < TN; j += 4) {
            int n = n0 + tx * TN + j;
            float4 v;
            v.x = acc[i][j + 0] + bias[n + 0];
            v.y = acc[i][j + 1] + bias[n + 1];
            v.z = acc[i][j + 2] + bias[n + 2];
            v.w = acc[i][j + 3] + bias[n + 3];
            if (RELU) {
                v.x = fmaxf(v.x, 0.0f);
                v.y = fmaxf(v.y, 0.0f);
                v.z = fmaxf(v.z, 0.0f);
                v.w = fmaxf(v.w, 0.0f);
            }
            *reinterpret_cast<float4*>(&C[row + n]) = v;
        }
    }
}

// ---------------- attention: logits -> softmax -> mixture, per-row loss -------
__global__ void attn_kernel(const float* __restrict__ query,
                            const float* __restrict__ keys,
                            const float* __restrict__ vals,
                            float* __restrict__ tower_in,
                            float* __restrict__ loss_row) {
    int b = blockIdx.x;
    int tid = threadIdx.x;           // 256 threads, 8 warps
    int wid = tid >> 5, lane = tid & 31;

    float part[NE];
#pragma unroll
    for (int e = 0; e < NE; e++) part[e] = 0.0f;

    for (int k = tid; k < DKE; k += 256) {
        float qv = query[(long)b * DKE + k];
#pragma unroll
        for (int e = 0; e < NE; e++)
            part[e] += qv * keys[((long)e * BSZ + b) * DKE + k];
    }
#pragma unroll
    for (int e = 0; e < NE; e++) {
#pragma unroll
        for (int off = 16; off > 0; off >>= 1)
            part[e] += __shfl_down_sync(0xffffffffu, part[e], off);
    }

    __shared__ float warpsum[8][NE];
    __shared__ float attn_s[NE];
    if (lane == 0) {
#pragma unroll
        for (int e = 0; e < NE; e++) warpsum[wid][e] = part[e];
    }
    __syncthreads();

    if (tid == 0) {
        float logits[NE];
#pragma unroll
        for (int e = 0; e < NE; e++) {
            float s = 0.0f;
            for (int w = 0; w < 8; w++) s += warpsum[w][e];
            logits[e] = s;
        }
        float mx = logits[0];
#pragma unroll
        for (int e = 1; e < NE; e++) mx = fmaxf(mx, logits[e]);
        float den = 0.0f;
        float ex[NE];
#pragma unroll
        for (int e = 0; e < NE; e++) { ex[e] = expf(logits[e] - mx); den += ex[e]; }
        float inv = 1.0f / den;
        float lsum = 0.0f;
#pragma unroll
        for (int e = 0; e < NE; e++) {
            float a = ex[e] * inv;
            attn_s[e] = a;
            float lg = logf(a + 1e-10f);
            lg = fminf(fmaxf(lg, -6.0f), 0.0f);
            lsum += lg;
        }
        loss_row[b] = lsum;
    }
    __syncthreads();

    for (int k = tid; k < DKE; k += 256) {
        float acc = 0.0f;
#pragma unroll
        for (int e = 0; e < NE; e++)
            acc += attn_s[e] * vals[((long)e * BSZ + b) * DKE + k];
        tower_in[(long)b * DKE + k] = acc;
    }
}

// ---------------- q head: (B,256) @ (256,1) + bt2, one warp per row -----------
__global__ void qhead_kernel(const float* __restrict__ h2,
                             const float* __restrict__ Wt2,
                             const float* __restrict__ bt2,
                             float* __restrict__ out) {
    int warp = (blockIdx.x * blockDim.x + threadIdx.x) >> 5;
    int lane = threadIdx.x & 31;
    if (warp >= BSZ) return;
    float s = 0.0f;
#pragma unroll
    for (int k = lane; k < 256; k += 32)
        s += h2[(long)warp * 256 + k] * Wt2[k];
#pragma unroll
    for (int off = 16; off > 0; off >>= 1)
        s += __shfl_down_sync(0xffffffffu, s, off);
    if (lane == 0) out[warp] = s + bt2[0];
}

// ---------------- deterministic loss reduction --------------------------------
__global__ void loss_kernel(const float* __restrict__ loss_row,
                            float* __restrict__ out, int out_size) {
    __shared__ float sm[256];
    int tid = threadIdx.x;
    float s = 0.0f;
    for (int i = tid; i < BSZ; i += 256) s += loss_row[i];
    sm[tid] = s;
    __syncthreads();
    for (int off = 128; off > 0; off >>= 1) {
        if (tid < off) sm[tid] += sm[tid + off];
        __syncthreads();
    }
    if (tid == 0 && out_size > BSZ)
        out[BSZ] = -(sm[0] / (float)BSZ) * 0.3f;
}

// ---------------- launch -------------------------------------------------------
extern "C" void kernel_launch(void* const* d_in, const int* in_sizes, int n_in,
                              void* d_out, int out_size) {
    const float* state  = (const float*)d_in[0];
    const float* act    = (const float*)d_in[1];
    const float* rep_W0 = (const float*)d_in[2];
    const float* rep_b0 = (const float*)d_in[3];
    const float* rep_W1 = (const float*)d_in[4];
    const float* rep_b1 = (const float*)d_in[5];
    const float* emb    = (const float*)d_in[6];
    const float* Wk0    = (const float*)d_in[7];
    const float* bk0    = (const float*)d_in[8];
    const float* Wk1    = (const float*)d_in[9];
    const float* bk1    = (const float*)d_in[10];
    const float* Wv0    = (const float*)d_in[11];
    const float* bv0    = (const float*)d_in[12];
    const float* Wv1    = (const float*)d_in[13];
    const float* bv1    = (const float*)d_in[14];
    const float* Wt0    = (const float*)d_in[15];
    const float* bt0    = (const float*)d_in[16];
    const float* Wt1    = (const float*)d_in[17];
    const float* bt1    = (const float*)d_in[18];
    const float* Wt2    = (const float*)d_in[19];
    const float* bt2    = (const float*)d_in[20];
    float* out = (float*)d_out;

    float *x, *query, *reph, *rep, *hk, *hv, *keys, *vals, *tin, *h1, *h2, *lrow;
    cudaGetSymbolAddress((void**)&x, g_x);
    cudaGetSymbolAddress((void**)&query, g_query);
    cudaGetSymbolAddress((void**)&reph, g_reph);
    cudaGetSymbolAddress((void**)&rep, g_rep);
    cudaGetSymbolAddress((void**)&hk, g_hk);
    cudaGetSymbolAddress((void**)&hv, g_hv);
    cudaGetSymbolAddress((void**)&keys, g_keys);
    cudaGetSymbolAddress((void**)&vals, g_vals);
    cudaGetSymbolAddress((void**)&tin, g_tin);
    cudaGetSymbolAddress((void**)&h1, g_h1);
    cudaGetSymbolAddress((void**)&h2, g_h2);
    cudaGetSymbolAddress((void**)&lrow, g_lossrow);

    // 0) prep
    prep_kernel<<<BSZ, 256>>>(state, act, emb, x, query);

    // 1) rep_h = relu(x @ rep_W0 + b0)      (4096x576)(576x1024)
    sgemm_kernel<true><<<dim3(DREP / BN, BSZ / BM, 1), 256>>>(
        x, rep_W0, rep_b0, reph, BSZ, DREP, XD, 0, 0, 0, 0);

    // 2) rep = rep_h @ rep_W1 + b1          (4096x1024)(1024x1024)
    sgemm_kernel<false><<<dim3(DREP / BN, BSZ / BM, 1), 256>>>(
        reph, rep_W1, rep_b1, rep, BSZ, DREP, DREP, 0, 0, 0, 0);

    // 3) hk[e] = relu(rep @ Wk0[e] + bk0[e]),  hv likewise  (batched z=16)
    sgemm_kernel<true><<<dim3(DH / BN, BSZ / BM, NE), 256>>>(
        rep, Wk0, bk0, hk, BSZ, DH, DREP,
        0, (long)DREP * DH, DH, (long)BSZ * DH);
    sgemm_kernel<true><<<dim3(DH / BN, BSZ / BM, NE), 256>>>(
        rep, Wv0, bv0, hv, BSZ, DH, DREP,
        0, (long)DREP * DH, DH, (long)BSZ * DH);

    // 4) keys[e] = hk[e] @ Wk1[e] + bk1[e],  vals likewise
    sgemm_kernel<false><<<dim3(DKE / BN, BSZ / BM, NE), 256>>>(
        hk, Wk1, bk1, keys, BSZ, DKE, DH,
        (long)BSZ * DH, (long)DH * DKE, DKE, (long)BSZ * DKE);
    sgemm_kernel<false><<<dim3(DKE / BN, BSZ / BM, NE), 256>>>(
        hv, Wv1, bv1, vals, BSZ, DKE, DH,
        (long)BSZ * DH, (long)DH * DKE, DKE, (long)BSZ * DKE);

    // 5) attention + mixture + per-row loss
    attn_kernel<<<BSZ, 256>>>(query, keys, vals, tin, lrow);

    // 6) tower
    sgemm_kernel<true><<<dim3(512 / BN, BSZ / BM, 1), 256>>>(
        tin, Wt0, bt0, h1, BSZ, 512, DKE, 0, 0, 0, 0);
    sgemm_kernel<true><<<dim3(256 / BN, BSZ / BM, 1), 256>>>(
        h1, Wt1, bt1, h2, BSZ, 256, 512, 0, 0, 0, 0);

    // 7) q head + loss
    qhead_kernel<<<(BSZ * 32 + 255) / 256, 256>>>(h2, Wt2, bt2, out);
    loss_kernel<<<1, 256>>>(lrow, out, out_size);
}

// round 8
// speedup vs baseline: 5.1373x; 5.1373x over previous
#include <cuda_runtime.h>
#include <cuda_bf16.h>
#include <cstdint>
#include <math.h>

// Problem constants
#define BSZ   4096
#define OBS   512
#define ACT_D 64
#define NT    10
#define NE    16
#define DREP  1024
#define DH    1024
#define DKE   512
#define XD    (OBS + ACT_D)   // 576
#define SW    (OBS + NT)      // 522

// ===================== helpers =====================
__device__ __forceinline__ uint32_t smem_u32(const void* p) {
    uint32_t a;
    asm("{ .reg .u64 t; cvta.to.shared.u64 t, %1; cvt.u32.u64 %0, t; }"
        : "=r"(a) : "l"(p));
    return a;
}
__device__ __forceinline__ void cp16(uint32_t dst, const void* src) {
    asm volatile("cp.async.cg.shared.global [%0], [%1], 16;" :: "r"(dst), "l"(src));
}
#define CP_COMMIT() asm volatile("cp.async.commit_group;" ::: "memory")
#define CP_WAIT0()  asm volatile("cp.async.wait_group 0;" ::: "memory")
#define CP_WAIT1()  asm volatile("cp.async.wait_group 1;" ::: "memory")

__device__ __forceinline__ void ldsm4(uint32_t* r, uint32_t addr) {
    asm volatile("ldmatrix.sync.aligned.m8n8.x4.shared.b16 {%0,%1,%2,%3}, [%4];"
                 : "=r"(r[0]), "=r"(r[1]), "=r"(r[2]), "=r"(r[3]) : "r"(addr));
}
__device__ __forceinline__ void mma16816(float* d, const uint32_t* a,
                                         uint32_t b0, uint32_t b1) {
    asm volatile(
        "mma.sync.aligned.m16n8k16.row.col.f32.bf16.bf16.f32 "
        "{%0,%1,%2,%3}, {%4,%5,%6,%7}, {%8,%9}, {%0,%1,%2,%3};"
        : "+f"(d[0]), "+f"(d[1]), "+f"(d[2]), "+f"(d[3])
        : "r"(a[0]), "r"(a[1]), "r"(a[2]), "r"(a[3]), "r"(b0), "r"(b1));
}

__device__ __forceinline__ void split2(float v, __nv_bfloat16& h, __nv_bfloat16& l) {
    h = __float2bfloat16(v);
    l = __float2bfloat16(v - __bfloat162float(h));
}

// ===================== scratch (static device globals) =====================
__device__ __nv_bfloat16 g_xh[(size_t)BSZ * XD], g_xl[(size_t)BSZ * XD];
__device__ float g_query[(size_t)BSZ * DKE];
__device__ __nv_bfloat16 g_rhh[(size_t)BSZ * DREP], g_rhl[(size_t)BSZ * DREP];
__device__ __nv_bfloat16 g_rsh[(size_t)BSZ * DREP], g_rsl[(size_t)BSZ * DREP];
__device__ __nv_bfloat16 g_hkh[(size_t)NE * BSZ * DH], g_hkl[(size_t)NE * BSZ * DH];
__device__ __nv_bfloat16 g_hvh[(size_t)NE * BSZ * DH], g_hvl[(size_t)NE * BSZ * DH];
__device__ float g_keys[(size_t)NE * BSZ * DKE], g_vals[(size_t)NE * BSZ * DKE];
__device__ __nv_bfloat16 g_tih[(size_t)BSZ * DKE], g_til[(size_t)BSZ * DKE];
__device__ __nv_bfloat16 g_h1h[(size_t)BSZ * 512], g_h1l[(size_t)BSZ * 512];
__device__ float g_h2[(size_t)BSZ * 256];
__device__ float g_lrow[BSZ];
// transposed split weights ([N,K] bf16)
__device__ __nv_bfloat16 g_W0h[(size_t)DREP * XD],  g_W0l[(size_t)DREP * XD];
__device__ __nv_bfloat16 g_W1h[(size_t)DREP * DREP], g_W1l[(size_t)DREP * DREP];
__device__ __nv_bfloat16 g_Wk0h[(size_t)NE * DH * DREP], g_Wk0l[(size_t)NE * DH * DREP];
__device__ __nv_bfloat16 g_Wv0h[(size_t)NE * DH * DREP], g_Wv0l[(size_t)NE * DH * DREP];
__device__ __nv_bfloat16 g_Wk1h[(size_t)NE * DKE * DH], g_Wk1l[(size_t)NE * DKE * DH];
__device__ __nv_bfloat16 g_Wv1h[(size_t)NE * DKE * DH], g_Wv1l[(size_t)NE * DKE * DH];
__device__ __nv_bfloat16 g_Wt0h[(size_t)512 * DKE], g_Wt0l[(size_t)512 * DKE];
__device__ __nv_bfloat16 g_Wt1h[(size_t)256 * 512], g_Wt1l[(size_t)256 * 512];

// ===================== prep: x split + query ==============================
__global__ void prep_kernel(const float* __restrict__ state,
                            const float* __restrict__ act,
                            const float* __restrict__ emb,
                            __nv_bfloat16* __restrict__ xh,
                            __nv_bfloat16* __restrict__ xl,
                            float* __restrict__ query) {
    int b = blockIdx.x;
    int tid = threadIdx.x;
    __shared__ int task_s;
    for (int i = tid; i < XD; i += blockDim.x) {
        float v = (i < OBS) ? state[(size_t)b * SW + i] : act[(size_t)b * ACT_D + (i - OBS)];
        __nv_bfloat16 h, l;
        split2(v, h, l);
        xh[(size_t)b * XD + i] = h;
        xl[(size_t)b * XD + i] = l;
    }
    if (tid == 0) {
        float best = -1e30f; int idx = 0;
        for (int t = 0; t < NT; t++) {
            float v = state[(size_t)b * SW + OBS + t];
            if (v > best) { best = v; idx = t; }
        }
        task_s = idx;
    }
    __syncthreads();
    int task = task_s;
    for (int k = tid; k < DKE; k += blockDim.x)
        query[(size_t)b * DKE + k] = tanhf(emb[task * DKE + k]);
}

// ===================== weight transpose + split: [K,N] -> [N,K] ===========
__global__ void wtrans_kernel(const float* __restrict__ W,
                              __nv_bfloat16* __restrict__ Th,
                              __nv_bfloat16* __restrict__ Tl,
                              int K, int N) {
    int z = blockIdx.z;
    W  += (size_t)z * K * N;
    Th += (size_t)z * K * N;
    Tl += (size_t)z * K * N;
    __shared__ float t[32][33];
    int n0 = blockIdx.x * 32, k0 = blockIdx.y * 32;
    int tx = threadIdx.x, ty = threadIdx.y;
    for (int i = ty; i < 32; i += 8)
        t[i][tx] = W[(size_t)(k0 + i) * N + n0 + tx];
    __syncthreads();
    for (int i = ty; i < 32; i += 8) {
        float v = t[tx][i];   // = W[k0+tx][n0+i]
        __nv_bfloat16 h, l;
        split2(v, h, l);
        Th[(size_t)(n0 + i) * K + k0 + tx] = h;
        Tl[(size_t)(n0 + i) * K + k0 + tx] = l;
    }
}

// ===================== mma.sync split-bf16 GEMM ============================
// C[4096, N] = A[4096, K] @ B^T  (A [M,K] row-major, B [N,K] row-major, both
// K-contiguous -> row.col mma operands). Split pairs (Ah,Al),(Bh,Bl); 3 MMA
// passes: AhBh + AhBl + AlBh.  CTA tile 128x128, BK=32, double-buffered
// cp.async smem with XOR swizzle.  Epilogue direct from c-fragments.

#define STG 32768            // Ah 8K | Al 8K | Bh 8K | Bl 8K
#define OFF_AH 0
#define OFF_AL 8192
#define OFF_BH 16384
#define OFF_BL 24576
#define SM_REQ (2 * STG)

// smem byte offset for (row, 16B-chunk) with conflict-free swizzle
__device__ __forceinline__ uint32_t swz(int r, int c) {
    return (uint32_t)(r * 64 + ((c ^ ((r >> 1) & 3)) << 4));
}

template <bool RELU, bool SPLIT>
__global__ void __launch_bounds__(256)
gemm_mma(const __nv_bfloat16* __restrict__ Ah, const __nv_bfloat16* __restrict__ Al,
         const __nv_bfloat16* __restrict__ Bh, const __nv_bfloat16* __restrict__ Bl,
         const float* __restrict__ bias,
         float* __restrict__ Cf, __nv_bfloat16* __restrict__ Ch, __nv_bfloat16* __restrict__ Cl,
         int N, int K, long sA, long sB, long sBias, long sC) {
    extern __shared__ char sm_raw[];
    uint32_t sb = smem_u32(sm_raw);

    int tid = threadIdx.x, lane = tid & 31, wid = tid >> 5;
    int z = blockIdx.z;
    const char* aH = (const char*)(Ah + (size_t)z * sA);
    const char* aL = (const char*)(Al + (size_t)z * sA);
    const char* bH = (const char*)(Bh + (size_t)z * sB);
    const char* bL = (const char*)(Bl + (size_t)z * sB);
    bias += (size_t)z * sBias;
    size_t coff = (size_t)z * sC;

    int m0 = blockIdx.y * 128, n0 = blockIdx.x * 128;
    int wm = wid & 1, wn = wid >> 1;       // 2 x 4 warps, warp tile 64x32

    size_t rsb = (size_t)K * 2;            // global row stride bytes
    aH += (size_t)m0 * rsb;  aL += (size_t)m0 * rsb;
    bH += (size_t)n0 * rsb;  bL += (size_t)n0 * rsb;

    float acc[4][4][4];
#pragma unroll
    for (int i = 0; i < 4; i++)
#pragma unroll
        for (int j = 0; j < 4; j++)
#pragma unroll
            for (int q = 0; q < 4; q++) acc[i][j][q] = 0.0f;

    int NC = K >> 5;   // K/32 chunks

    // ---- pipelined load: 128 rows x 4 chunks per tensor; 512 iters over 256 thr
    auto load_stage = [&](int c, int buf) {
        uint32_t s = sb + buf * STG;
        size_t gk = (size_t)c * 64;  // 32 elems * 2B
#pragma unroll
        for (int p = tid; p < 512; p += 256) {
            int r = p >> 2, ch = p & 3;
            uint32_t off = swz(r, ch);
            size_t g = (size_t)r * rsb + gk + ch * 16;
            cp16(s + OFF_AH + off, aH + g);
            cp16(s + OFF_AL + off, aL + g);
            cp16(s + OFF_BH + off, bH + g);
            cp16(s + OFF_BL + off, bL + g);
        }
    };

    load_stage(0, 0);
    CP_COMMIT();

    for (int c = 0; c < NC; c++) {
        if (c + 1 < NC) { load_stage(c + 1, (c + 1) & 1); CP_COMMIT(); CP_WAIT1(); }
        else           { CP_WAIT0(); }
        __syncthreads();

        uint32_t s = sb + (c & 1) * STG;
#pragma unroll
        for (int ks = 0; ks < 2; ks++) {
            // A fragments (Ah, Al): 4 m16 tiles each
            uint32_t fah[4][4], fal[4][4];
            int arow = wm * 64 + (lane & 7) + ((lane >> 3) & 1) * 8;
            int achk = ks * 2 + (lane >> 4);
#pragma unroll
            for (int mt = 0; mt < 4; mt++) {
                uint32_t off = swz(arow + mt * 16, achk);
                ldsm4(fah[mt], s + OFF_AH + off);
                ldsm4(fal[mt], s + OFF_AL + off);
            }
            int brow_base = wn * 32 + (lane & 7) + (lane >> 4) * 8;
            int bchk = ks * 2 + ((lane >> 3) & 1);
#pragma unroll
            for (int nt2 = 0; nt2 < 2; nt2++) {
                uint32_t fbh[4], fbl[4];
                uint32_t off = swz(brow_base + nt2 * 16, bchk);
                ldsm4(fbh, s + OFF_BH + off);
                ldsm4(fbl, s + OFF_BL + off);
#pragma unroll
                for (int mt = 0; mt < 4; mt++) {
                    mma16816(acc[mt][nt2 * 2 + 0], fah[mt], fbh[0], fbh[1]);
                    mma16816(acc[mt][nt2 * 2 + 1], fah[mt], fbh[2], fbh[3]);
                    mma16816(acc[mt][nt2 * 2 + 0], fah[mt], fbl[0], fbl[1]);
                    mma16816(acc[mt][nt2 * 2 + 1], fah[mt], fbl[2], fbl[3]);
                    mma16816(acc[mt][nt2 * 2 + 0], fal[mt], fbh[0], fbh[1]);
                    mma16816(acc[mt][nt2 * 2 + 1], fal[mt], fbh[2], fbh[3]);
                }
            }
        }
        __syncthreads();
    }

    // ---- epilogue: straight from c-fragments ----
    int mbase = m0 + wm * 64 + (lane >> 2);
    int nbase = n0 + wn * 32 + (lane & 3) * 2;
#pragma unroll
    for (int nt = 0; nt < 4; nt++) {
        int n = nbase + nt * 8;
        float b0 = bias[n], b1 = bias[n + 1];
#pragma unroll
        for (int mt = 0; mt < 4; mt++) {
            int m = mbase + mt * 16;
            float v00 = acc[mt][nt][0] + b0, v01 = acc[mt][nt][1] + b1;
            float v10 = acc[mt][nt][2] + b0, v11 = acc[mt][nt][3] + b1;
            if (RELU) {
                v00 = fmaxf(v00, 0.0f); v01 = fmaxf(v01, 0.0f);
                v10 = fmaxf(v10, 0.0f); v11 = fmaxf(v11, 0.0f);
            }
            if (SPLIT) {
                __nv_bfloat162 h2a, l2a, h2b, l2b;
                split2(v00, h2a.x, l2a.x); split2(v01, h2a.y, l2a.y);
                split2(v10, h2b.x, l2b.x); split2(v11, h2b.y, l2b.y);
                *(__nv_bfloat162*)(Ch + coff + (size_t)m * N + n)       = h2a;
                *(__nv_bfloat162*)(Cl + coff + (size_t)m * N + n)       = l2a;
                *(__nv_bfloat162*)(Ch + coff + (size_t)(m + 8) * N + n) = h2b;
                *(__nv_bfloat162*)(Cl + coff + (size_t)(m + 8) * N + n) = l2b;
            } else {
                *(float2*)(Cf + coff + (size_t)m * N + n)       = make_float2(v00, v01);
                *(float2*)(Cf + coff + (size_t)(m + 8) * N + n) = make_float2(v10, v11);
            }
        }
    }
}

// ===================== attention + mixture (split-bf16 out) ===============
__global__ void attn_kernel(const float* __restrict__ query,
                            const float* __restrict__ keys,
                            const float* __restrict__ vals,
                            __nv_bfloat16* __restrict__ tih,
                            __nv_bfloat16* __restrict__ til,
                            float* __restrict__ loss_row) {
    int b = blockIdx.x;
    int tid = threadIdx.x;
    int wid = tid >> 5, lane = tid & 31;

    float part[NE];
#pragma unroll
    for (int e = 0; e < NE; e++) part[e] = 0.0f;
    for (int k = tid; k < DKE; k += 256) {
        float qv = query[(size_t)b * DKE + k];
#pragma unroll
        for (int e = 0; e < NE; e++)
            part[e] += qv * keys[((size_t)e * BSZ + b) * DKE + k];
    }
#pragma unroll
    for (int e = 0; e < NE; e++) {
#pragma unroll
        for (int off = 16; off > 0; off >>= 1)
            part[e] += __shfl_down_sync(0xffffffffu, part[e], off);
    }
    __shared__ float warpsum[8][NE];
    __shared__ float attn_s[NE];
    if (lane == 0) {
#pragma unroll
        for (int e = 0; e < NE; e++) warpsum[wid][e] = part[e];
    }
    __syncthreads();
    if (tid == 0) {
        float logits[NE];
#pragma unroll
        for (int e = 0; e < NE; e++) {
            float s = 0.0f;
            for (int w = 0; w < 8; w++) s += warpsum[w][e];
            logits[e] = s;
        }
        float mx = logits[0];
#pragma unroll
        for (int e = 1; e < NE; e++) mx = fmaxf(mx, logits[e]);
        float den = 0.0f, ex[NE];
#pragma unroll
        for (int e = 0; e < NE; e++) { ex[e] = expf(logits[e] - mx); den += ex[e]; }
        float inv = 1.0f / den;
        float lsum = 0.0f;
#pragma unroll
        for (int e = 0; e < NE; e++) {
            float a = ex[e] * inv;
            attn_s[e] = a;
            float lg = logf(a + 1e-10f);
            lg = fminf(fmaxf(lg, -6.0f), 0.0f);
            lsum += lg;
        }
        loss_row[b] = lsum;
    }
    __syncthreads();
    for (int k = tid; k < DKE; k += 256) {
        float acc = 0.0f;
#pragma unroll
        for (int e = 0; e < NE; e++)
            acc += attn_s[e] * vals[((size_t)e * BSZ + b) * DKE + k];
        __nv_bfloat16 h, l;
        split2(acc, h, l);
        tih[(size_t)b * DKE + k] = h;
        til[(size_t)b * DKE + k] = l;
    }
}

// ===================== q head + loss =====================================
__global__ void qhead_kernel(const float* __restrict__ h2,
                             const float* __restrict__ Wt2,
                             const float* __restrict__ bt2,
                             float* __restrict__ out) {
    int warp = (blockIdx.x * blockDim.x + threadIdx.x) >> 5;
    int lane = threadIdx.x & 31;
    if (warp >= BSZ) return;
    float s = 0.0f;
#pragma unroll
    for (int k = lane; k < 256; k += 32)
        s += h2[(size_t)warp * 256 + k] * Wt2[k];
#pragma unroll
    for (int off = 16; off > 0; off >>= 1)
        s += __shfl_down_sync(0xffffffffu, s, off);
    if (lane == 0) out[warp] = s + bt2[0];
}

__global__ void loss_kernel(const float* __restrict__ loss_row,
                            float* __restrict__ out, int out_size) {
    __shared__ float sm[256];
    int tid = threadIdx.x;
    float s = 0.0f;
    for (int i = tid; i < BSZ; i += 256) s += loss_row[i];
    sm[tid] = s;
    __syncthreads();
    for (int off = 128; off > 0; off >>= 1) {
        if (tid < off) sm[tid] += sm[tid + off];
        __syncthreads();
    }
    if (tid == 0 && out_size > BSZ)
        out[BSZ] = -(sm[0] / (float)BSZ) * 0.3f;
}

// ===================== launch =============================================
#define SYM(var, sym) cudaGetSymbolAddress((void**)&var, sym)

extern "C" void kernel_launch(void* const* d_in, const int* in_sizes, int n_in,
                              void* d_out, int out_size) {
    const float* state  = (const float*)d_in[0];
    const float* act    = (const float*)d_in[1];
    const float* rep_W0 = (const float*)d_in[2];
    const float* rep_b0 = (const float*)d_in[3];
    const float* rep_W1 = (const float*)d_in[4];
    const float* rep_b1 = (const float*)d_in[5];
    const float* emb    = (const float*)d_in[6];
    const float* Wk0    = (const float*)d_in[7];
    const float* bk0    = (const float*)d_in[8];
    const float* Wk1    = (const float*)d_in[9];
    const float* bk1    = (const float*)d_in[10];
    const float* Wv0    = (const float*)d_in[11];
    const float* bv0    = (const float*)d_in[12];
    const float* Wv1    = (const float*)d_in[13];
    const float* bv1    = (const float*)d_in[14];
    const float* Wt0    = (const float*)d_in[15];
    const float* bt0    = (const float*)d_in[16];
    const float* Wt1    = (const float*)d_in[17];
    const float* bt1    = (const float*)d_in[18];
    const float* Wt2    = (const float*)d_in[19];
    const float* bt2    = (const float*)d_in[20];
    float* out = (float*)d_out;

    __nv_bfloat16 *xh, *xl, *rhh, *rhl, *rsh, *rsl, *hkh, *hkl, *hvh, *hvl;
    __nv_bfloat16 *tih, *til, *h1h, *h1l;
    __nv_bfloat16 *W0h, *W0l, *W1h, *W1l, *Wk0h, *Wk0l, *Wv0h, *Wv0l;
    __nv_bfloat16 *Wk1h, *Wk1l, *Wv1h, *Wv1l, *Wt0h, *Wt0l, *Wt1h, *Wt1l;
    float *query, *keys, *vals, *h2, *lrow;
    SYM(xh, g_xh);   SYM(xl, g_xl);   SYM(query, g_query);
    SYM(rhh, g_rhh); SYM(rhl, g_rhl); SYM(rsh, g_rsh); SYM(rsl, g_rsl);
    SYM(hkh, g_hkh); SYM(hkl, g_hkl); SYM(hvh, g_hvh); SYM(hvl, g_hvl);
    SYM(keys, g_keys); SYM(vals, g_vals);
    SYM(tih, g_tih); SYM(til, g_til); SYM(h1h, g_h1h); SYM(h1l, g_h1l);
    SYM(h2, g_h2);   SYM(lrow, g_lrow);
    SYM(W0h, g_W0h); SYM(W0l, g_W0l); SYM(W1h, g_W1h); SYM(W1l, g_W1l);
    SYM(Wk0h, g_Wk0h); SYM(Wk0l, g_Wk0l); SYM(Wv0h, g_Wv0h); SYM(Wv0l, g_Wv0l);
    SYM(Wk1h, g_Wk1h); SYM(Wk1l, g_Wk1l); SYM(Wv1h, g_Wv1h); SYM(Wv1l, g_Wv1l);
    SYM(Wt0h, g_Wt0h); SYM(Wt0l, g_Wt0l); SYM(Wt1h, g_Wt1h); SYM(Wt1l, g_Wt1l);

    cudaFuncSetAttribute(gemm_mma<true, true>,   cudaFuncAttributeMaxDynamicSharedMemorySize, SM_REQ);
    cudaFuncSetAttribute(gemm_mma<false, true>,  cudaFuncAttributeMaxDynamicSharedMemorySize, SM_REQ);
    cudaFuncSetAttribute(gemm_mma<false, false>, cudaFuncAttributeMaxDynamicSharedMemorySize, SM_REQ);
    cudaFuncSetAttribute(gemm_mma<true, false>,  cudaFuncAttributeMaxDynamicSharedMemorySize, SM_REQ);

    dim3 tb(32, 8);
    // prep + weight conversion
    prep_kernel<<<BSZ, 256>>>(state, act, emb, xh, xl, query);
    wtrans_kernel<<<dim3(DREP / 32, XD / 32, 1), tb>>>(rep_W0, W0h, W0l, XD, DREP);
    wtrans_kernel<<<dim3(DREP / 32, DREP / 32, 1), tb>>>(rep_W1, W1h, W1l, DREP, DREP);
    wtrans_kernel<<<dim3(DH / 32, DREP / 32, NE), tb>>>(Wk0, Wk0h, Wk0l, DREP, DH);
    wtrans_kernel<<<dim3(DH / 32, DREP / 32, NE), tb>>>(Wv0, Wv0h, Wv0l, DREP, DH);
    wtrans_kernel<<<dim3(DKE / 32, DH / 32, NE), tb>>>(Wk1, Wk1h, Wk1l, DH, DKE);
    wtrans_kernel<<<dim3(DKE / 32, DH / 32, NE), tb>>>(Wv1, Wv1h, Wv1l, DH, DKE);
    wtrans_kernel<<<dim3(512 / 32, DKE / 32, 1), tb>>>(Wt0, Wt0h, Wt0l, DKE, 512);
    wtrans_kernel<<<dim3(256 / 32, 512 / 32, 1), tb>>>(Wt1, Wt1h, Wt1l, 512, 256);

    // rep MLP
    gemm_mma<true, true><<<dim3(DREP / 128, BSZ / 128, 1), 256, SM_REQ>>>(
        xh, xl, W0h, W0l, rep_b0, nullptr, rhh, rhl, DREP, XD, 0, 0, 0, 0);
    gemm_mma<false, true><<<dim3(DREP / 128, BSZ / 128, 1), 256, SM_REQ>>>(
        rhh, rhl, W1h, W1l, rep_b1, nullptr, rsh, rsl, DREP, DREP, 0, 0, 0, 0);
    // expert layer 1 (k, v), batched z=16
    gemm_mma<true, true><<<dim3(DH / 128, BSZ / 128, NE), 256, SM_REQ>>>(
        rsh, rsl, Wk0h, Wk0l, bk0, nullptr, hkh, hkl, DH, DREP,
        0, (long)DH * DREP, DH, (long)BSZ * DH);
    gemm_mma<true, true><<<dim3(DH / 128, BSZ / 128, NE), 256, SM_REQ>>>(
        rsh, rsl, Wv0h, Wv0l, bv0, nullptr, hvh, hvl, DH, DREP,
        0, (long)DH * DREP, DH, (long)BSZ * DH);
    // expert layer 2 (k, v) -> fp32 keys/vals
    gemm_mma<false, false><<<dim3(DKE / 128, BSZ / 128, NE), 256, SM_REQ>>>(
        hkh, hkl, Wk1h, Wk1l, bk1, keys, nullptr, nullptr, DKE, DH,
        (long)BSZ * DH, (long)DKE * DH, DKE, (long)BSZ * DKE);
    gemm_mma<false, false><<<dim3(DKE / 128, BSZ / 128, NE), 256, SM_REQ>>>(
        hvh, hvl, Wv1h, Wv1l, bv1, vals, nullptr, nullptr, DKE, DH,
        (long)BSZ * DH, (long)DKE * DH, DKE, (long)BSZ * DKE);
    // attention + mixture
    attn_kernel<<<BSZ, 256>>>(query, keys, vals, tih, til, lrow);
    // tower
    gemm_mma<true, true><<<dim3(512 / 128, BSZ / 128, 1), 256, SM_REQ>>>(
        tih, til, Wt0h, Wt0l, bt0, nullptr, h1h, h1l, 512, DKE, 0, 0, 0, 0);
    gemm_mma<true, false><<<dim3(256 / 128, BSZ / 128, 1), 256, SM_REQ>>>(
        h1h, h1l, Wt1h, Wt1l, bt1, h2, nullptr, nullptr, 256, 512, 0, 0, 0, 0);
    // head + loss
    qhead_kernel<<<(BSZ * 32 + 255) / 256, 256>>>(h2, Wt2, bt2, out);
    loss_kernel<<<1, 256>>>(lrow, out, out_size);
}